// round 3
// baseline (speedup 1.0000x reference)
#include <cuda_runtime.h>
#include <math.h>
#include <stdint.h>

#define NPTS      524288
#define GRIDSZ    512
#define NC        36
#define KIN       129
#define K1PAD     136
#define HID       256
#define NOUT      129
#define NOUT_PAD  144
#define TB        128
#define NTHREADS  512

#define HS_STRIDE 140          // %32=12 -> conflict-free A frags
#define H1_STRIDE 260          // %32=4
#define WS_STRIDE 264          // %32=8  -> conflict-free B frags
#define WS_BUF    (32*WS_STRIDE)              // 8448 floats per 32-row slab
#define SM_A_FLOATS (TB*H1_STRIDE)            // 33280 (union: hs then h1s)
#define SM_WS_OFF   SM_A_FLOATS
#define SM_B1_OFF   (SM_WS_OFF + 2*WS_BUF)    // 50176
#define SM_B2_OFF   (SM_B1_OFF + HID)         // 50432
#define SM_FLOATS   (SM_B2_OFF + NOUT_PAD)    // 50576
#define SMEM_BYTES  (SM_FLOATS*4)             // 202304 B

// device-global scratch (sanctioned mechanism)
__device__ float g_planesT[3*GRIDSZ*GRIDSZ*NC];   // [i][y][x][c]
__device__ float g_linesT[3*GRIDSZ*NC];           // [i][l][c]
__device__ float g_W1p[K1PAD*HID];                // tf32-rounded, zero-padded rows
__device__ float g_W2p[HID*NOUT_PAD];             // tf32-rounded, zero-padded cols

__device__ __forceinline__ unsigned f2tf(float x) {
    unsigned r; asm("cvt.rna.tf32.f32 %0, %1;" : "=r"(r) : "f"(x)); return r;
}
__device__ __forceinline__ float f2tff(float x) { return __uint_as_float(f2tf(x)); }

__global__ void transpose_kernel(const float* __restrict__ planes,
                                 const float* __restrict__ lines) {
    int tid = blockIdx.x * blockDim.x + threadIdx.x;
    const int NPLANE = 3*GRIDSZ*GRIDSZ;
    if (tid < NPLANE) {
        int x = tid & (GRIDSZ-1);
        int y = (tid >> 9) & (GRIDSZ-1);
        int i = tid / (GRIDSZ*GRIDSZ);
        float* dst = g_planesT + tid*NC;
        const float* src = planes + ((long)i*NC*GRIDSZ*GRIDSZ) + (long)y*GRIDSZ + x;
        #pragma unroll
        for (int c = 0; c < NC; c++)
            dst[c] = src[(long)c*GRIDSZ*GRIDSZ];
    } else {
        int t2 = tid - NPLANE;
        if (t2 < 3*GRIDSZ) {
            int j = t2 & (GRIDSZ-1);
            int i = t2 >> 9;
            float* dst = g_linesT + t2*NC;
            const float* src = lines + (long)i*NC*GRIDSZ + j;
            #pragma unroll
            for (int c = 0; c < NC; c++)
                dst[c] = src[(long)c*GRIDSZ];
        }
    }
}

__global__ void pack_weights_kernel(const float* __restrict__ W1,
                                    const float* __restrict__ W2) {
    int idx = blockIdx.x * blockDim.x + threadIdx.x;
    const int T1 = K1PAD*HID;        // 34816
    const int T2 = HID*NOUT_PAD;     // 36864
    if (idx < T1) {
        int k = idx >> 8, n = idx & 255;
        g_W1p[idx] = (k < KIN) ? f2tff(W1[k*HID + n]) : 0.f;
    } else if (idx < T1 + T2) {
        int j = idx - T1;
        int k = j / NOUT_PAD, n = j - k*NOUT_PAD;
        g_W2p[j] = (n < NOUT) ? f2tff(W2[k*NOUT + n]) : 0.f;
    }
}

__device__ __forceinline__ void mma_tf32(float c[4], unsigned a0, unsigned a1,
                                         unsigned a2, unsigned a3,
                                         unsigned b0, unsigned b1) {
    asm volatile(
        "mma.sync.aligned.m16n8k8.row.col.f32.tf32.tf32.f32 "
        "{%0,%1,%2,%3},{%4,%5,%6,%7},{%8,%9},{%0,%1,%2,%3};"
        : "+f"(c[0]), "+f"(c[1]), "+f"(c[2]), "+f"(c[3])
        : "r"(a0), "r"(a1), "r"(a2), "r"(a3), "r"(b0), "r"(b1));
}

__device__ __forceinline__ float softplus100(float z) {
    float y = 100.f * z;
    return 0.01f * (fmaxf(y, 0.f) + __logf(1.f + __expf(-fabsf(y))));
}

__device__ __forceinline__ void cp16(uint32_t dst, const float* src) {
    asm volatile("cp.async.cg.shared.global [%0], [%1], 16;" :: "r"(dst), "l"(src));
}
__device__ __forceinline__ void cp_commit() {
    asm volatile("cp.async.commit_group;");
}
__device__ __forceinline__ void cp_wait0() {
    asm volatile("cp.async.wait_group 0;" ::: "memory");
}

__global__ void __launch_bounds__(NTHREADS, 1)
tensosdf_main(const float* __restrict__ xyz,
              const float* __restrict__ b1, const float* __restrict__ b2,
              float* __restrict__ out) {
    extern __shared__ float smem[];
    float* sA  = smem;                 // hs[128][140] then h1s[128][260]
    float* ws  = smem + SM_WS_OFF;
    float* b1s = smem + SM_B1_OFF;
    float* b2s = smem + SM_B2_OFF;
    const uint32_t ws_s = (uint32_t)__cvta_generic_to_shared(ws);

    const int tid  = threadIdx.x;
    const int lane = tid & 31;
    const int warp = tid >> 5;
    const int pbase = blockIdx.x * TB;
    const int g = lane >> 2;
    const int t = lane & 3;

    // ---- biases ----
    if (tid < HID) b1s[tid] = b1[tid];
    else if (tid < HID + NOUT_PAD) {
        int c = tid - HID;
        b2s[c] = (c < NOUT) ? b2[c] : 0.f;
    }

    // ---- stage first W1 slab (async, overlaps gather) ----
    {
        const float* src0 = g_W1p;
        #pragma unroll
        for (int e = 0; e < 4; e++) {
            int idx = tid + e * NTHREADS;
            int kk = idx >> 6, n4 = (idx & 63) << 2;
            cp16(ws_s + (uint32_t)(kk*WS_STRIDE + n4)*4u, src0 + kk*HID + n4);
        }
        cp_commit();
    }

    // ---- gather phase: 4 threads per point ----
    {
        const int p   = tid >> 2;
        const int sub = tid & 3;
        const int gp  = pbase + p;
        float xn[3];
        xn[0] = 2.f * xyz[gp*3+0] - 1.f;
        xn[1] = 2.f * xyz[gp*3+1] - 1.f;
        xn[2] = 2.f * xyz[gp*3+2] - 1.f;
        float* hrow = sA + p * HS_STRIDE;

        const int m0s[3] = {0, 0, 1};
        const int m1s[3] = {1, 2, 2};
        const int vms[3] = {2, 1, 0};
        #pragma unroll
        for (int i = 0; i < 3; i++) {
            float gx = xn[m0s[i]], gy = xn[m1s[i]], gl = xn[vms[i]];
            float px = (gx + 1.f) * 0.5f * 511.f;
            float py = (gy + 1.f) * 0.5f * 511.f;
            float pl = (gl + 1.f) * 0.5f * 511.f;
            int ix = min(max((int)floorf(px), 0), 510);
            int iy = min(max((int)floorf(py), 0), 510);
            int il = min(max((int)floorf(pl), 0), 510);
            float wx = px - (float)ix, wy = py - (float)iy, wl = pl - (float)il;
            const float* pb = g_planesT + (((i*GRIDSZ + iy)*GRIDSZ) + ix) * NC;
            const float* lb = g_linesT + (i*GRIDSZ + il) * NC;
            #pragma unroll
            for (int j = 0; j < 9; j++) {
                int c = sub * 9 + j;
                float f00 = pb[c];
                float f01 = pb[NC + c];
                float f10 = pb[GRIDSZ*NC + c];
                float f11 = pb[GRIDSZ*NC + NC + c];
                float fx0 = f00 + wx * (f01 - f00);
                float fx1 = f10 + wx * (f11 - f10);
                float pf  = fx0 + wy * (fx1 - fx0);
                float l0  = lb[c];
                float lf  = l0 + wl * (lb[NC + c] - l0);
                hrow[i*NC + c] = f2tff(pf * lf);
            }
        }
        if (sub < 3) {
            float v = xn[sub];
            hrow[108 + sub] = f2tff(v);
            float fr = 1.f;
            #pragma unroll
            for (int fi = 0; fi < 3; fi++) {
                float s, c;
                sincosf(v * fr, &s, &c);
                hrow[111 + 6*fi + sub] = f2tff(s);
                hrow[114 + 6*fi + sub] = f2tff(c);
                fr *= 2.f;
            }
        } else {
            #pragma unroll
            for (int c = KIN; c < HS_STRIDE; c++) hrow[c] = 0.f;
        }
    }

    cp_wait0();
    __syncthreads();

    // ================= GEMM1: 4m x 4n warp tiling =================
    const int mt = warp & 3;          // m-tile: 32 rows
    const int nq = warp >> 2;         // n-quarter: 64 cols
    const int arow = mt * 32;

    float acc[2][8][4];
    #pragma unroll
    for (int i = 0; i < 2; i++)
        #pragma unroll
        for (int j = 0; j < 8; j++)
            #pragma unroll
            for (int q = 0; q < 4; q++) acc[i][j][q] = 0.f;

    #pragma unroll
    for (int c = 0; c < 5; c++) {
        int buf = c & 1;
        if (c < 4) {   // prefetch next slab
            int rows = (c == 3) ? 8 : 32;
            const float* src0 = g_W1p + (c+1)*32*HID;
            uint32_t dbase = ws_s + (uint32_t)((buf^1)*WS_BUF)*4u;
            int nops = rows * 64;
            for (int idx = tid; idx < nops; idx += NTHREADS) {
                int kk = idx >> 6, n4 = (idx & 63) << 2;
                cp16(dbase + (uint32_t)(kk*WS_STRIDE + n4)*4u, src0 + kk*HID + n4);
            }
            cp_commit();
        }
        int nks = (c < 4) ? 4 : 1;
        #pragma unroll
        for (int kk8 = 0; kk8 < 4; kk8++) {
            if (kk8 >= nks) break;
            const float* Ab = sA + (arow + g)*HS_STRIDE + c*32 + kk8*8 + t;
            unsigned a00 = __float_as_uint(Ab[0]);
            unsigned a01 = __float_as_uint(Ab[8*HS_STRIDE]);
            unsigned a02 = __float_as_uint(Ab[4]);
            unsigned a03 = __float_as_uint(Ab[8*HS_STRIDE + 4]);
            const float* Ab2 = Ab + 16*HS_STRIDE;
            unsigned a10 = __float_as_uint(Ab2[0]);
            unsigned a11 = __float_as_uint(Ab2[8*HS_STRIDE]);
            unsigned a12 = __float_as_uint(Ab2[4]);
            unsigned a13 = __float_as_uint(Ab2[8*HS_STRIDE + 4]);
            const float* Bb = ws + buf*WS_BUF + (kk8*8 + t)*WS_STRIDE + nq*64 + g;
            #pragma unroll
            for (int nf = 0; nf < 8; nf++) {
                unsigned bb0 = __float_as_uint(Bb[nf*8]);
                unsigned bb1 = __float_as_uint(Bb[4*WS_STRIDE + nf*8]);
                mma_tf32(acc[0][nf], a00, a01, a02, a03, bb0, bb1);
                mma_tf32(acc[1][nf], a10, a11, a12, a13, bb0, bb1);
            }
        }
        if (c < 4) cp_wait0();
        __syncthreads();
    }

    // epilogue 1: bias + softplus -> h1s (tf32-rounded)
    #pragma unroll
    for (int mf = 0; mf < 2; mf++) {
        #pragma unroll
        for (int nf = 0; nf < 8; nf++) {
            int col = nq*64 + nf*8 + 2*t;
            float bb0 = b1s[col], bb1 = b1s[col+1];
            int row0 = arow + mf*16 + g;
            float r0 = f2tff(softplus100(acc[mf][nf][0] + bb0));
            float r1 = f2tff(softplus100(acc[mf][nf][1] + bb1));
            float r2 = f2tff(softplus100(acc[mf][nf][2] + bb0));
            float r3 = f2tff(softplus100(acc[mf][nf][3] + bb1));
            *(float2*)(sA + row0*H1_STRIDE + col)     = make_float2(r0, r1);
            *(float2*)(sA + (row0+8)*H1_STRIDE + col) = make_float2(r2, r3);
        }
    }

    // stage first W2 slab
    {
        const float* src0 = g_W2p;
        for (int idx = tid; idx < 32*36; idx += NTHREADS) {
            int kk = idx / 36, n4 = (idx - kk*36) << 2;
            cp16(ws_s + (uint32_t)(kk*WS_STRIDE + n4)*4u, src0 + kk*NOUT_PAD + n4);
        }
        cp_commit();
    }
    cp_wait0();
    __syncthreads();

    // ================= GEMM2: 8m x 2n warp tiling =================
    const int mt2 = warp & 7;
    const int nh2 = warp >> 3;
    const int arow2 = mt2 * 16;

    float acc2[9][4];
    #pragma unroll
    for (int i = 0; i < 9; i++)
        #pragma unroll
        for (int q = 0; q < 4; q++) acc2[i][q] = 0.f;

    #pragma unroll
    for (int c = 0; c < 8; c++) {
        int buf = c & 1;
        if (c < 7) {
            const float* src0 = g_W2p + (c+1)*32*NOUT_PAD;
            uint32_t dbase = ws_s + (uint32_t)((buf^1)*WS_BUF)*4u;
            for (int idx = tid; idx < 32*36; idx += NTHREADS) {
                int kk = idx / 36, n4 = (idx - kk*36) << 2;
                cp16(dbase + (uint32_t)(kk*WS_STRIDE + n4)*4u, src0 + kk*NOUT_PAD + n4);
            }
            cp_commit();
        }
        #pragma unroll
        for (int kk8 = 0; kk8 < 4; kk8++) {
            const float* Ab = sA + (arow2 + g)*H1_STRIDE + c*32 + kk8*8 + t;
            unsigned a0 = __float_as_uint(Ab[0]);
            unsigned a1 = __float_as_uint(Ab[8*H1_STRIDE]);
            unsigned a2 = __float_as_uint(Ab[4]);
            unsigned a3 = __float_as_uint(Ab[8*H1_STRIDE + 4]);
            const float* Bb = ws + buf*WS_BUF + (kk8*8 + t)*WS_STRIDE + nh2*72 + g;
            #pragma unroll
            for (int nf = 0; nf < 9; nf++) {
                unsigned bb0 = __float_as_uint(Bb[nf*8]);
                unsigned bb1 = __float_as_uint(Bb[4*WS_STRIDE + nf*8]);
                mma_tf32(acc2[nf], a0, a1, a2, a3, bb0, bb1);
            }
        }
        if (c < 7) cp_wait0();
        __syncthreads();
    }

    // epilogue 2: bias + store
    #pragma unroll
    for (int nf = 0; nf < 9; nf++) {
        int col = nh2*72 + nf*8 + 2*t;
        float o0 = acc2[nf][0] + b2s[col];
        float o1 = acc2[nf][1] + b2s[col+1];
        float o2 = acc2[nf][2] + b2s[col];
        float o3 = acc2[nf][3] + b2s[col+1];
        int r0 = (pbase + arow2 + g) * NOUT;
        int r1 = (pbase + arow2 + g + 8) * NOUT;
        if (col < NOUT)     { out[r0 + col]     = o0; out[r1 + col]     = o2; }
        if (col + 1 < NOUT) { out[r0 + col + 1] = o1; out[r1 + col + 1] = o3; }
    }
}

extern "C" void kernel_launch(void* const* d_in, const int* in_sizes, int n_in,
                              void* d_out, int out_size) {
    const float* xyz    = (const float*)d_in[0];
    const float* planes = (const float*)d_in[1];
    const float* lines  = (const float*)d_in[2];
    const float* W1     = (const float*)d_in[3];
    const float* b1     = (const float*)d_in[4];
    const float* W2     = (const float*)d_in[5];
    const float* b2     = (const float*)d_in[6];
    float* out = (float*)d_out;

    static bool attr_set = false;
    if (!attr_set) {
        cudaFuncSetAttribute(tensosdf_main,
                             cudaFuncAttributeMaxDynamicSharedMemorySize, SMEM_BYTES);
        attr_set = true;
    }

    const int ntrans = 3*GRIDSZ*GRIDSZ + 3*GRIDSZ;
    transpose_kernel<<<(ntrans + 255) / 256, 256>>>(planes, lines);
    const int npack = K1PAD*HID + HID*NOUT_PAD;
    pack_weights_kernel<<<(npack + 255) / 256, 256>>>(W1, W2);
    tensosdf_main<<<NPTS / TB, NTHREADS, SMEM_BYTES>>>(xyz, b1, b2, out);
}

// round 4
// speedup vs baseline: 1.9840x; 1.9840x over previous
#include <cuda_runtime.h>
#include <math.h>
#include <stdint.h>

#define NPTS      524288
#define GRIDSZ    512
#define NC        36
#define KIN       129
#define K1PAD     136
#define HID       256
#define NOUT      129
#define NOUT_PAD  144
#define TB        128
#define NTHREADS  512

#define HS_STRIDE 140          // %32=12 -> conflict-free A frags; 560B = 16B aligned
#define H1_STRIDE 260          // %32=4
#define WS_STRIDE 264          // %32=8  -> conflict-free B frags
#define WS_BUF    (32*WS_STRIDE)              // 8448 floats per 32-row slab
#define SM_A_FLOATS (TB*H1_STRIDE)            // 33280 (union: hs then h1s)
#define SM_WS_OFF   SM_A_FLOATS
#define SM_B1_OFF   (SM_WS_OFF + 2*WS_BUF)    // 50176
#define SM_B2_OFF   (SM_B1_OFF + HID)         // 50432
#define SM_FLOATS   (SM_B2_OFF + NOUT_PAD)    // 50576
#define SMEM_BYTES  (SM_FLOATS*4)             // 202304 B

// device-global scratch (sanctioned mechanism)
__device__ float g_planesT[3*GRIDSZ*GRIDSZ*NC];   // [i][y][x][c]
__device__ float g_linesT[3*GRIDSZ*NC];           // [i][l][c]
__device__ float g_W1p[K1PAD*HID];                // tf32-rounded, zero-padded rows
__device__ float g_W2p[HID*NOUT_PAD];             // tf32-rounded, zero-padded cols

__device__ __forceinline__ unsigned f2tf(float x) {
    unsigned r; asm("cvt.rna.tf32.f32 %0, %1;" : "=r"(r) : "f"(x)); return r;
}
__device__ __forceinline__ float f2tff(float x) { return __uint_as_float(f2tf(x)); }

// ---------------- coalesced plane transpose ----------------
// each warp: 32 consecutive (i,y,x) cells; stage via smem; contiguous STG.128 out
__global__ void __launch_bounds__(256) transpose_planes(const float* __restrict__ planes) {
    __shared__ float tile[8][32*37];
    int wid = threadIdx.x >> 5, lane = threadIdx.x & 31;
    int gw = blockIdx.x * 8 + wid;              // 0..24575
    int cell0 = gw * 32;
    int i = cell0 / (GRIDSZ*GRIDSZ);
    int rem = cell0 - i*GRIDSZ*GRIDSZ;
    int y = rem >> 9;
    int x0 = rem & (GRIDSZ-1);                  // multiple of 32
    const float* src = planes + (long)i*NC*GRIDSZ*GRIDSZ + (long)y*GRIDSZ + x0 + lane;
    float* t = tile[wid];
    #pragma unroll
    for (int c = 0; c < NC; c++)
        t[lane*37 + c] = src[(long)c*GRIDSZ*GRIDSZ];
    __syncwarp();
    float* dst = g_planesT + (long)cell0 * NC;
    #pragma unroll
    for (int k = 0; k < 9; k++) {
        int flat = k*32 + lane;                 // 0..287 uint4 index
        int fo = flat * 4;
        int cc = fo / NC, c = fo - cc*NC;       // c multiple of 4
        float4 v = make_float4(t[cc*37+c], t[cc*37+c+1], t[cc*37+c+2], t[cc*37+c+3]);
        *(float4*)(dst + fo) = v;
    }
}

__global__ void transpose_lines(const float* __restrict__ lines) {
    int t2 = blockIdx.x * blockDim.x + threadIdx.x;
    if (t2 < 3*GRIDSZ) {
        int j = t2 & (GRIDSZ-1);
        int i = t2 >> 9;
        float* dst = g_linesT + t2*NC;
        const float* src = lines + (long)i*NC*GRIDSZ + j;
        #pragma unroll
        for (int c = 0; c < NC; c++)
            dst[c] = src[(long)c*GRIDSZ];
    }
}

__global__ void pack_weights_kernel(const float* __restrict__ W1,
                                    const float* __restrict__ W2) {
    int idx = blockIdx.x * blockDim.x + threadIdx.x;
    const int T1 = K1PAD*HID;        // 34816
    const int T2 = HID*NOUT_PAD;     // 36864
    if (idx < T1) {
        int k = idx >> 8, n = idx & 255;
        g_W1p[idx] = (k < KIN) ? f2tff(W1[k*HID + n]) : 0.f;
    } else if (idx < T1 + T2) {
        int j = idx - T1;
        int k = j / NOUT_PAD, n = j - k*NOUT_PAD;
        g_W2p[j] = (n < NOUT) ? f2tff(W2[k*NOUT + n]) : 0.f;
    }
}

__device__ __forceinline__ void mma_tf32(float c[4], unsigned a0, unsigned a1,
                                         unsigned a2, unsigned a3,
                                         unsigned b0, unsigned b1) {
    asm volatile(
        "mma.sync.aligned.m16n8k8.row.col.f32.tf32.tf32.f32 "
        "{%0,%1,%2,%3},{%4,%5,%6,%7},{%8,%9},{%0,%1,%2,%3};"
        : "+f"(c[0]), "+f"(c[1]), "+f"(c[2]), "+f"(c[3])
        : "r"(a0), "r"(a1), "r"(a2), "r"(a3), "r"(b0), "r"(b1));
}

__device__ __forceinline__ float softplus100(float z) {
    float y = 100.f * z;
    return 0.01f * (fmaxf(y, 0.f) + __logf(1.f + __expf(-fabsf(y))));
}

__device__ __forceinline__ void cp16(uint32_t dst, const float* src) {
    asm volatile("cp.async.cg.shared.global [%0], [%1], 16;" :: "r"(dst), "l"(src));
}
__device__ __forceinline__ void cp_commit() {
    asm volatile("cp.async.commit_group;");
}
__device__ __forceinline__ void cp_wait0() {
    asm volatile("cp.async.wait_group 0;" ::: "memory");
}

__global__ void __launch_bounds__(NTHREADS, 1)
tensosdf_main(const float* __restrict__ xyz,
              const float* __restrict__ b1, const float* __restrict__ b2,
              float* __restrict__ out) {
    extern __shared__ float smem[];
    float* sA  = smem;                 // hs[128][140] then h1s[128][260]
    float* ws  = smem + SM_WS_OFF;
    float* b1s = smem + SM_B1_OFF;
    float* b2s = smem + SM_B2_OFF;
    const uint32_t ws_s = (uint32_t)__cvta_generic_to_shared(ws);

    const int tid  = threadIdx.x;
    const int lane = tid & 31;
    const int warp = tid >> 5;
    const int pbase = blockIdx.x * TB;
    const int g = lane >> 2;
    const int t = lane & 3;

    // ---- biases ----
    if (tid < HID) b1s[tid] = b1[tid];
    else if (tid < HID + NOUT_PAD) {
        int c = tid - HID;
        b2s[c] = (c < NOUT) ? b2[c] : 0.f;
    }

    // ---- stage first W1 slab (async, overlaps gather) ----
    {
        const float* src0 = g_W1p;
        #pragma unroll
        for (int e = 0; e < 4; e++) {
            int idx = tid + e * NTHREADS;
            int kk = idx >> 6, n4 = (idx & 63) << 2;
            cp16(ws_s + (uint32_t)(kk*WS_STRIDE + n4)*4u, src0 + kk*HID + n4);
        }
        cp_commit();
    }

    // ---- gather phase: warp-cooperative, vectorized ----
    // warp handles 8 points; per point: 27 lanes = 3 planes x 9 lanes x 4 channels (LDG.128)
    {
        const unsigned FULL = 0xffffffffu;
        float vload = 0.f;
        int base3 = (pbase + warp*8)*3;
        if (lane < 24) vload = xyz[base3 + lane];

        const int i_of = (lane < 9) ? 0 : ((lane < 18) ? 1 : 2);
        const int cj = (lane - i_of*9) * 4;
        const bool act = lane < 27;

        #pragma unroll
        for (int pi = 0; pi < 8; pi++) {
            float x0 = __shfl_sync(FULL, vload, pi*3+0);
            float x1 = __shfl_sync(FULL, vload, pi*3+1);
            float x2 = __shfl_sync(FULL, vload, pi*3+2);
            float xn0 = 2.f*x0 - 1.f;
            float xn1 = 2.f*x1 - 1.f;
            float xn2 = 2.f*x2 - 1.f;
            float* hrow = sA + (warp*8 + pi) * HS_STRIDE;

            if (act) {
                // MAT_MODE = {(0,1),(0,2),(1,2)}; VEC_MODE = {2,1,0}
                float gx = (i_of == 2) ? xn1 : xn0;
                float gy = (i_of == 0) ? xn1 : xn2;
                float gl = (i_of == 0) ? xn2 : ((i_of == 1) ? xn1 : xn0);
                float px = (gx + 1.f) * 0.5f * 511.f;
                float py = (gy + 1.f) * 0.5f * 511.f;
                float pl = (gl + 1.f) * 0.5f * 511.f;
                int ix = min(max((int)floorf(px), 0), 510);
                int iy = min(max((int)floorf(py), 0), 510);
                int il = min(max((int)floorf(pl), 0), 510);
                float wx = px - (float)ix, wy = py - (float)iy, wl = pl - (float)il;
                const float* pb = g_planesT + (((i_of*GRIDSZ + iy)*GRIDSZ) + ix)*NC + cj;
                const float* lb = g_linesT + (i_of*GRIDSZ + il)*NC + cj;
                float4 f00 = *(const float4*)pb;
                float4 f01 = *(const float4*)(pb + NC);
                float4 f10 = *(const float4*)(pb + GRIDSZ*NC);
                float4 f11 = *(const float4*)(pb + GRIDSZ*NC + NC);
                float4 l0  = *(const float4*)lb;
                float4 l1  = *(const float4*)(lb + NC);
                float4 r;
                {
                    float fx0 = f00.x + wx*(f01.x - f00.x);
                    float fx1 = f10.x + wx*(f11.x - f10.x);
                    r.x = f2tff((fx0 + wy*(fx1 - fx0)) * (l0.x + wl*(l1.x - l0.x)));
                    fx0 = f00.y + wx*(f01.y - f00.y);
                    fx1 = f10.y + wx*(f11.y - f10.y);
                    r.y = f2tff((fx0 + wy*(fx1 - fx0)) * (l0.y + wl*(l1.y - l0.y)));
                    fx0 = f00.z + wx*(f01.z - f00.z);
                    fx1 = f10.z + wx*(f11.z - f10.z);
                    r.z = f2tff((fx0 + wy*(fx1 - fx0)) * (l0.z + wl*(l1.z - l0.z)));
                    fx0 = f00.w + wx*(f01.w - f00.w);
                    fx1 = f10.w + wx*(f11.w - f10.w);
                    r.w = f2tff((fx0 + wy*(fx1 - fx0)) * (l0.w + wl*(l1.w - l0.w)));
                }
                *(float4*)(hrow + i_of*NC + cj) = r;
            }

            // PE + zero-pad: lanes 0..31 -> hrow[108..139]
            float pv;
            if (lane < 3) {
                pv = (lane == 0) ? xn0 : ((lane == 1) ? xn1 : xn2);
            } else if (lane < 21) {
                int j = lane - 3;
                int f = j / 6;
                int rr = j - 6*f;
                int d = rr % 3;
                float xv = ((d == 0) ? xn0 : ((d == 1) ? xn1 : xn2)) * (float)(1 << f);
                pv = (rr < 3) ? __sinf(xv) : __cosf(xv);
            } else {
                pv = 0.f;
            }
            hrow[108 + lane] = f2tff(pv);
        }
    }

    cp_wait0();
    __syncthreads();

    // ================= GEMM1: 4m x 4n warp tiling =================
    const int mt = warp & 3;          // m-tile: 32 rows
    const int nq = warp >> 2;         // n-quarter: 64 cols
    const int arow = mt * 32;

    float acc[2][8][4];
    #pragma unroll
    for (int i = 0; i < 2; i++)
        #pragma unroll
        for (int j = 0; j < 8; j++)
            #pragma unroll
            for (int q = 0; q < 4; q++) acc[i][j][q] = 0.f;

    #pragma unroll
    for (int c = 0; c < 5; c++) {
        int buf = c & 1;
        if (c < 4) {   // prefetch next slab
            int rows = (c == 3) ? 8 : 32;
            const float* src0 = g_W1p + (c+1)*32*HID;
            uint32_t dbase = ws_s + (uint32_t)((buf^1)*WS_BUF)*4u;
            int nops = rows * 64;
            for (int idx = tid; idx < nops; idx += NTHREADS) {
                int kk = idx >> 6, n4 = (idx & 63) << 2;
                cp16(dbase + (uint32_t)(kk*WS_STRIDE + n4)*4u, src0 + kk*HID + n4);
            }
            cp_commit();
        }
        int nks = (c < 4) ? 4 : 1;
        #pragma unroll
        for (int kk8 = 0; kk8 < 4; kk8++) {
            if (kk8 >= nks) break;
            const float* Ab = sA + (arow + g)*HS_STRIDE + c*32 + kk8*8 + t;
            unsigned a00 = __float_as_uint(Ab[0]);
            unsigned a01 = __float_as_uint(Ab[8*HS_STRIDE]);
            unsigned a02 = __float_as_uint(Ab[4]);
            unsigned a03 = __float_as_uint(Ab[8*HS_STRIDE + 4]);
            const float* Ab2 = Ab + 16*HS_STRIDE;
            unsigned a10 = __float_as_uint(Ab2[0]);
            unsigned a11 = __float_as_uint(Ab2[8*HS_STRIDE]);
            unsigned a12 = __float_as_uint(Ab2[4]);
            unsigned a13 = __float_as_uint(Ab2[8*HS_STRIDE + 4]);
            const float* Bb = ws + buf*WS_BUF + (kk8*8 + t)*WS_STRIDE + nq*64 + g;
            #pragma unroll
            for (int nf = 0; nf < 8; nf++) {
                unsigned bb0 = __float_as_uint(Bb[nf*8]);
                unsigned bb1 = __float_as_uint(Bb[4*WS_STRIDE + nf*8]);
                mma_tf32(acc[0][nf], a00, a01, a02, a03, bb0, bb1);
                mma_tf32(acc[1][nf], a10, a11, a12, a13, bb0, bb1);
            }
        }
        if (c < 4) cp_wait0();
        __syncthreads();
    }

    // epilogue 1: bias + softplus -> h1s (tf32-rounded)
    #pragma unroll
    for (int mf = 0; mf < 2; mf++) {
        #pragma unroll
        for (int nf = 0; nf < 8; nf++) {
            int col = nq*64 + nf*8 + 2*t;
            float bb0 = b1s[col], bb1 = b1s[col+1];
            int row0 = arow + mf*16 + g;
            float r0 = f2tff(softplus100(acc[mf][nf][0] + bb0));
            float r1 = f2tff(softplus100(acc[mf][nf][1] + bb1));
            float r2 = f2tff(softplus100(acc[mf][nf][2] + bb0));
            float r3 = f2tff(softplus100(acc[mf][nf][3] + bb1));
            *(float2*)(sA + row0*H1_STRIDE + col)     = make_float2(r0, r1);
            *(float2*)(sA + (row0+8)*H1_STRIDE + col) = make_float2(r2, r3);
        }
    }

    // stage first W2 slab
    {
        const float* src0 = g_W2p;
        for (int idx = tid; idx < 32*36; idx += NTHREADS) {
            int kk = idx / 36, n4 = (idx - kk*36) << 2;
            cp16(ws_s + (uint32_t)(kk*WS_STRIDE + n4)*4u, src0 + kk*NOUT_PAD + n4);
        }
        cp_commit();
    }
    cp_wait0();
    __syncthreads();

    // ================= GEMM2: 8m x 2n warp tiling =================
    const int mt2 = warp & 7;
    const int nh2 = warp >> 3;
    const int arow2 = mt2 * 16;

    float acc2[9][4];
    #pragma unroll
    for (int i = 0; i < 9; i++)
        #pragma unroll
        for (int q = 0; q < 4; q++) acc2[i][q] = 0.f;

    #pragma unroll
    for (int c = 0; c < 8; c++) {
        int buf = c & 1;
        if (c < 7) {
            const float* src0 = g_W2p + (c+1)*32*NOUT_PAD;
            uint32_t dbase = ws_s + (uint32_t)((buf^1)*WS_BUF)*4u;
            for (int idx = tid; idx < 32*36; idx += NTHREADS) {
                int kk = idx / 36, n4 = (idx - kk*36) << 2;
                cp16(dbase + (uint32_t)(kk*WS_STRIDE + n4)*4u, src0 + kk*NOUT_PAD + n4);
            }
            cp_commit();
        }
        #pragma unroll
        for (int kk8 = 0; kk8 < 4; kk8++) {
            const float* Ab = sA + (arow2 + g)*H1_STRIDE + c*32 + kk8*8 + t;
            unsigned a0 = __float_as_uint(Ab[0]);
            unsigned a1 = __float_as_uint(Ab[8*H1_STRIDE]);
            unsigned a2 = __float_as_uint(Ab[4]);
            unsigned a3 = __float_as_uint(Ab[8*H1_STRIDE + 4]);
            const float* Bb = ws + buf*WS_BUF + (kk8*8 + t)*WS_STRIDE + nh2*72 + g;
            #pragma unroll
            for (int nf = 0; nf < 9; nf++) {
                unsigned bb0 = __float_as_uint(Bb[nf*8]);
                unsigned bb1 = __float_as_uint(Bb[4*WS_STRIDE + nf*8]);
                mma_tf32(acc2[nf], a0, a1, a2, a3, bb0, bb1);
            }
        }
        if (c < 7) cp_wait0();
        __syncthreads();
    }

    // epilogue 2: bias + store
    #pragma unroll
    for (int nf = 0; nf < 9; nf++) {
        int col = nh2*72 + nf*8 + 2*t;
        float o0 = acc2[nf][0] + b2s[col];
        float o1 = acc2[nf][1] + b2s[col+1];
        float o2 = acc2[nf][2] + b2s[col];
        float o3 = acc2[nf][3] + b2s[col+1];
        int r0 = (pbase + arow2 + g) * NOUT;
        int r1 = (pbase + arow2 + g + 8) * NOUT;
        if (col < NOUT)     { out[r0 + col]     = o0; out[r1 + col]     = o2; }
        if (col + 1 < NOUT) { out[r0 + col + 1] = o1; out[r1 + col + 1] = o3; }
    }
}

extern "C" void kernel_launch(void* const* d_in, const int* in_sizes, int n_in,
                              void* d_out, int out_size) {
    const float* xyz    = (const float*)d_in[0];
    const float* planes = (const float*)d_in[1];
    const float* lines  = (const float*)d_in[2];
    const float* W1     = (const float*)d_in[3];
    const float* b1     = (const float*)d_in[4];
    const float* W2     = (const float*)d_in[5];
    const float* b2     = (const float*)d_in[6];
    float* out = (float*)d_out;

    static bool attr_set = false;
    if (!attr_set) {
        cudaFuncSetAttribute(tensosdf_main,
                             cudaFuncAttributeMaxDynamicSharedMemorySize, SMEM_BYTES);
        attr_set = true;
    }

    // 3*512*512 cells / 32 per warp / 8 warps per block = 3072 blocks
    transpose_planes<<<3072, 256>>>(planes);
    transpose_lines<<<6, 256>>>(lines);
    const int npack = K1PAD*HID + HID*NOUT_PAD;
    pack_weights_kernel<<<(npack + 255) / 256, 256>>>(W1, W2);
    tensosdf_main<<<NPTS / TB, NTHREADS, SMEM_BYTES>>>(xyz, b1, b2, out);
}